// round 15
// baseline (speedup 1.0000x reference)
#include <cuda_runtime.h>
#include <cuda_fp16.h>
#include <cstdint>

#define BB 4
#define LL 2048
#define EE 1024
#define HH 16
#define DD 64
#define NTOK 8192            // BB*LL
#define WELEM 1048576        // EE*EE

// ---------------- scratch (device globals; no allocation allowed) -------------
__device__ __align__(16) float  g_partial[1024];
__device__ __align__(16) float  g_scale[4];
__device__ __align__(16) int8_t g_qw[4 * WELEM];           // q,k,v,o ternary weights
__device__ __align__(16) int8_t g_qx[3 * NTOK * EE];       // quantized activations
__device__ __align__(16) float  g_gamma[3 * NTOK];
__device__ __align__(16) __half g_projh[3 * NTOK * EE];    // q/k/v proj fp16 [B][H][L][D]
__device__ __align__(16) float  g_ctx[NTOK * EE];          // attention output [B][L][E]
__device__ __align__(16) int8_t g_qctx[NTOK * EE];
__device__ __align__(16) float  g_gctx[NTOK];

// ---------------- PTX helpers (standard sm_80+ instructions only) -------------
__device__ __forceinline__ uint32_t smem_u32(const void* p) {
    uint32_t a;
    asm("{ .reg .u64 t; cvta.to.shared.u64 t, %1; cvt.u32.u64 %0, t; }" : "=r"(a) : "l"(p));
    return a;
}
#define MMA_F16(c0, c1, c2, c3, a0, a1, a2, a3, b0, b1) \
    asm volatile("mma.sync.aligned.m16n8k16.row.col.f32.f16.f16.f32 " \
        "{%0,%1,%2,%3}, {%4,%5,%6,%7}, {%8,%9}, {%0,%1,%2,%3};" \
        : "+f"(c0), "+f"(c1), "+f"(c2), "+f"(c3) \
        : "r"(a0), "r"(a1), "r"(a2), "r"(a3), "r"(b0), "r"(b1))
#define MMA_S8(c0, c1, c2, c3, a0, a1, a2, a3, b0, b1) \
    asm volatile("mma.sync.aligned.m16n8k32.row.col.s32.s8.s8.s32 " \
        "{%0,%1,%2,%3}, {%4,%5,%6,%7}, {%8,%9}, {%0,%1,%2,%3};" \
        : "+r"(c0), "+r"(c1), "+r"(c2), "+r"(c3) \
        : "r"(a0), "r"(a1), "r"(a2), "r"(a3), "r"(b0), "r"(b1))
#define LDSM_X4(r0, r1, r2, r3, a) \
    asm volatile("ldmatrix.sync.aligned.m8n8.x4.shared.b16 {%0,%1,%2,%3}, [%4];" \
        : "=r"(r0), "=r"(r1), "=r"(r2), "=r"(r3) : "r"(a))
#define LDSM_X4_T(r0, r1, r2, r3, a) \
    asm volatile("ldmatrix.sync.aligned.m8n8.x4.trans.shared.b16 {%0,%1,%2,%3}, [%4];" \
        : "=r"(r0), "=r"(r1), "=r"(r2), "=r"(r3) : "r"(a))
// d = f16x2 {lo, hi}
#define PACK_F16X2(d, lo, hi) \
    asm("cvt.rn.f16x2.f32 %0, %1, %2;" : "=r"(d) : "f"(hi), "f"(lo))
#define EX2F(d, x) asm("ex2.approx.f32 %0, %1;" : "=f"(d) : "f"(x))
#define CP_ASYNC16(saddr, gaddr) \
    asm volatile("cp.async.cg.shared.global [%0], [%1], 16;" :: "r"(saddr), "l"(gaddr))
#define CP_COMMIT()  asm volatile("cp.async.commit_group;" ::: "memory")
#define CP_WAIT0()   asm volatile("cp.async.wait_group 0;" ::: "memory")

// ---------------- 1) weight abs-sum partials (256 blocks per tensor) ----------
__global__ void k_wsum(const float* __restrict__ inw, const float* __restrict__ outw) {
    int w = blockIdx.y;
    const float4* p = reinterpret_cast<const float4*>((w < 3) ? inw + (size_t)w * WELEM : outw);
    const int chunk4 = WELEM / 4 / 256;          // 1024 float4 per block
    int base = blockIdx.x * chunk4;
    float s = 0.f;
    for (int i = threadIdx.x; i < chunk4; i += 256) {
        float4 v = p[base + i];
        s += fabsf(v.x) + fabsf(v.y) + fabsf(v.z) + fabsf(v.w);
    }
    #pragma unroll
    for (int st = 16; st; st >>= 1) s += __shfl_xor_sync(~0u, s, st);
    __shared__ float sm[8];
    if ((threadIdx.x & 31) == 0) sm[threadIdx.x >> 5] = s;
    __syncthreads();
    if (threadIdx.x == 0) {
        float tot = 0.f;
        #pragma unroll
        for (int i = 0; i < 8; i++) tot += sm[i];
        g_partial[w * 256 + blockIdx.x] = tot;
    }
}

// ---------------- 3) ternarize weights; scale reduced in-block ----------------
// Each block covers 1024 consecutive weights (one tensor). Scale computed
// redundantly per block from g_partial; tensor-start blocks store g_scale.
__global__ void k_wquant(const float* __restrict__ inw, const float* __restrict__ outw) {
    const int w = (int)(blockIdx.x >> 10);           // 1024 blocks per tensor
    // block-reduce the 256 partials of tensor w
    float s = g_partial[w * 256 + threadIdx.x];
    #pragma unroll
    for (int st = 16; st; st >>= 1) s += __shfl_xor_sync(~0u, s, st);
    __shared__ float sm[8];
    if ((threadIdx.x & 31) == 0) sm[threadIdx.x >> 5] = s;
    __syncthreads();
    float tot = sm[0];
    #pragma unroll
    for (int i = 1; i < 8; i++) tot += sm[i];
    const float scale = fmaxf(tot * (1.f / (float)WELEM), 1e-5f);
    if ((blockIdx.x & 1023) == 0 && threadIdx.x == 0) g_scale[w] = scale;

    int idx4 = blockIdx.x * 256 + threadIdx.x;
    int idx = idx4 * 4;
    float4 v = (idx < 3 * WELEM)
        ? reinterpret_cast<const float4*>(inw)[idx4]
        : reinterpret_cast<const float4*>(outw)[idx4 - 3 * WELEM / 4];
    float inv = 1.f / scale;
    float q0 = fmaxf(-1.f, fminf(1.f, rintf(v.x * inv)));
    float q1 = fmaxf(-1.f, fminf(1.f, rintf(v.y * inv)));
    float q2 = fmaxf(-1.f, fminf(1.f, rintf(v.z * inv)));
    float q3 = fmaxf(-1.f, fminf(1.f, rintf(v.w * inv)));
    reinterpret_cast<char4*>(g_qw)[idx4] =
        make_char4((int8_t)q0, (int8_t)q1, (int8_t)q2, (int8_t)q3);
}

// ---------------- 4) activation quantization: warp-per-token ------------------
__device__ __forceinline__ void actq_warp(const float* xp, int8_t* qx, float* gam,
                                          int t, int lane) {
    const float4* x4 = reinterpret_cast<const float4*>(xp);
    float4 v4[8];
    float m = 0.f;
    #pragma unroll
    for (int i = 0; i < 8; i++) {
        v4[i] = x4[lane + i * 32];
        m = fmaxf(m, fmaxf(fmaxf(fabsf(v4[i].x), fabsf(v4[i].y)),
                           fmaxf(fabsf(v4[i].z), fabsf(v4[i].w))));
    }
    #pragma unroll
    for (int w = 16; w; w >>= 1) m = fmaxf(m, __shfl_xor_sync(~0u, m, w));
    float gamma = fmaxf(m, 1e-5f);
    float inv = 128.f / gamma;
    char4* q4 = reinterpret_cast<char4*>(qx);
    #pragma unroll
    for (int i = 0; i < 8; i++) {
        float q0 = fmaxf(-128.f, fminf(127.f, rintf(v4[i].x * inv)));
        float q1 = fmaxf(-128.f, fminf(127.f, rintf(v4[i].y * inv)));
        float q2 = fmaxf(-128.f, fminf(127.f, rintf(v4[i].z * inv)));
        float q3 = fmaxf(-128.f, fminf(127.f, rintf(v4[i].w * inv)));
        q4[lane + i * 32] = make_char4((int8_t)q0, (int8_t)q1, (int8_t)q2, (int8_t)q3);
    }
    if (lane == 0) gam[t] = gamma;
}

__global__ void k_actq_in(const float* __restrict__ q, const float* __restrict__ k,
                          const float* __restrict__ v) {
    int slot = blockIdx.y;
    const float* x = (slot == 0) ? q : (slot == 1) ? k : v;
    int wid = threadIdx.x >> 5, lane = threadIdx.x & 31;
    int t = blockIdx.x * 8 + wid;
    actq_warp(x + (size_t)t * EE,
              g_qx + (size_t)slot * NTOK * EE + (size_t)t * EE,
              g_gamma + slot * NTOK, t, lane);
}

__global__ void k_actq_ctx() {
    int wid = threadIdx.x >> 5, lane = threadIdx.x & 31;
    int t = blockIdx.x * 8 + wid;
    actq_warp(g_ctx + (size_t)t * EE, g_qctx + (size_t)t * EE, g_gctx, t, lane);
}

// ---------------- 5) q/k/v projection GEMM (int8 mma.sync, exact) -------------
// Epilogue emits fp16 Q/K/V (Q pre-scaled by 0.125*log2e), head-split.
#define PROJ_SAS 48

__global__ void __launch_bounds__(256) k_proj8(const float* __restrict__ in_bias) {
    __shared__ __align__(16) int8_t sA[2][128 * PROJ_SAS];
    __shared__ __align__(16) int8_t sB[2][128 * PROJ_SAS];
    const int z = blockIdx.z;
    const int8_t* Ag = g_qx + (size_t)z * NTOK * EE + (size_t)blockIdx.y * 128 * EE;
    const int8_t* Bg = g_qw + (size_t)z * WELEM + (size_t)blockIdx.x * 128 * EE;
    const int tid = threadIdx.x, wid = tid >> 5, lane = tid & 31;
    const int wm = wid & 1, wn = wid >> 1;
    const int crow = tid >> 1, chalf = tid & 1;

    CP_ASYNC16(smem_u32(&sA[0][crow * PROJ_SAS + chalf * 16]), Ag + crow * EE + chalf * 16);
    CP_ASYNC16(smem_u32(&sB[0][crow * PROJ_SAS + chalf * 16]), Bg + crow * EE + chalf * 16);
    CP_COMMIT();

    int acc[4][4][4] = {};
    const uint32_t lrow = lane & 15, lhalf = lane >> 4;

    for (int kt = 0; kt < 32; kt++) {
        CP_WAIT0();
        __syncthreads();
        const int buf = kt & 1;
        if (kt < 31) {
            CP_ASYNC16(smem_u32(&sA[buf ^ 1][crow * PROJ_SAS + chalf * 16]),
                       Ag + crow * EE + (kt + 1) * 32 + chalf * 16);
            CP_ASYNC16(smem_u32(&sB[buf ^ 1][crow * PROJ_SAS + chalf * 16]),
                       Bg + crow * EE + (kt + 1) * 32 + chalf * 16);
            CP_COMMIT();
        }
        uint32_t af[4][4];
        #pragma unroll
        for (int mt = 0; mt < 4; mt++) {
            uint32_t a = smem_u32(&sA[buf][(wm * 64 + mt * 16 + lrow) * PROJ_SAS + lhalf * 16]);
            LDSM_X4(af[mt][0], af[mt][1], af[mt][2], af[mt][3], a);
        }
        uint32_t bq[2][4];
        #pragma unroll
        for (int bp = 0; bp < 2; bp++) {
            uint32_t a = smem_u32(&sB[buf][(wn * 32 + bp * 16 + lrow) * PROJ_SAS + lhalf * 16]);
            LDSM_X4(bq[bp][0], bq[bp][1], bq[bp][2], bq[bp][3], a);
        }
        #pragma unroll
        for (int mt = 0; mt < 4; mt++)
            #pragma unroll
            for (int nt = 0; nt < 4; nt++) {
                const int bp = nt >> 1, sel = nt & 1;
                MMA_S8(acc[mt][nt][0], acc[mt][nt][1], acc[mt][nt][2], acc[mt][nt][3],
                       af[mt][0], af[mt][1], af[mt][2], af[mt][3],
                       bq[bp][sel], bq[bp][2 + sel]);
            }
    }

    // epilogue: scale + bias; for Q fold exact 0.125*log2(e); emit fp16
    const float qmul = (z == 0) ? 0.125f * 1.4426950408889634f : 1.f;
    const float wsc = g_scale[z] * 0.0078125f * qmul;   // /128
    __half* outp = g_projh + (size_t)z * NTOK * EE;
    #pragma unroll
    for (int mt = 0; mt < 4; mt++) {
        const int mlo = blockIdx.y * 128 + wm * 64 + mt * 16 + (lane >> 2);
        const int mhi = mlo + 8;
        const float sclo = wsc * g_gamma[z * NTOK + mlo];
        const float schi = wsc * g_gamma[z * NTOK + mhi];
        const int blo = mlo >> 11, llo = mlo & 2047;
        const int bhi = mhi >> 11, lhi = mhi & 2047;
        #pragma unroll
        for (int nt = 0; nt < 4; nt++) {
            const int n = blockIdx.x * 128 + wn * 32 + nt * 8 + (lane & 3) * 2;
            const int h = n >> 6, d = n & 63;
            const float fb0 = in_bias[z * EE + n] * qmul;
            const float fb1 = in_bias[z * EE + n + 1] * qmul;
            float v0 = (float)acc[mt][nt][0] * sclo + fb0;
            float v1 = (float)acc[mt][nt][1] * sclo + fb1;
            float v2 = (float)acc[mt][nt][2] * schi + fb0;
            float v3 = (float)acc[mt][nt][3] * schi + fb1;
            uint32_t plo, phi;
            PACK_F16X2(plo, v0, v1);
            PACK_F16X2(phi, v2, v3);
            *reinterpret_cast<uint32_t*>(
                &outp[((size_t)(blo * HH + h) * LL + llo) * DD + d]) = plo;
            *reinterpret_cast<uint32_t*>(
                &outp[((size_t)(bhi * HH + h) * LL + lhi) * DD + d]) = phi;
        }
    }
}

// ---------------- 7) output projection GEMM (int8 mma.sync, exact) ------------
__global__ void __launch_bounds__(256) k_oproj8(const float* __restrict__ o_bias,
                                                float* __restrict__ out) {
    __shared__ __align__(16) int8_t sA[2][128 * PROJ_SAS];
    __shared__ __align__(16) int8_t sB[2][128 * PROJ_SAS];
    const int8_t* Ag = g_qctx + (size_t)blockIdx.y * 128 * EE;
    const int8_t* Bg = g_qw + (size_t)3 * WELEM + (size_t)blockIdx.x * 128 * EE;
    const int tid = threadIdx.x, wid = tid >> 5, lane = tid & 31;
    const int wm = wid & 1, wn = wid >> 1;
    const int crow = tid >> 1, chalf = tid & 1;

    CP_ASYNC16(smem_u32(&sA[0][crow * PROJ_SAS + chalf * 16]), Ag + crow * EE + chalf * 16);
    CP_ASYNC16(smem_u32(&sB[0][crow * PROJ_SAS + chalf * 16]), Bg + crow * EE + chalf * 16);
    CP_COMMIT();

    int acc[4][4][4] = {};
    const uint32_t lrow = lane & 15, lhalf = lane >> 4;

    for (int kt = 0; kt < 32; kt++) {
        CP_WAIT0();
        __syncthreads();
        const int buf = kt & 1;
        if (kt < 31) {
            CP_ASYNC16(smem_u32(&sA[buf ^ 1][crow * PROJ_SAS + chalf * 16]),
                       Ag + crow * EE + (kt + 1) * 32 + chalf * 16);
            CP_ASYNC16(smem_u32(&sB[buf ^ 1][crow * PROJ_SAS + chalf * 16]),
                       Bg + crow * EE + (kt + 1) * 32 + chalf * 16);
            CP_COMMIT();
        }
        uint32_t af[4][4];
        #pragma unroll
        for (int mt = 0; mt < 4; mt++) {
            uint32_t a = smem_u32(&sA[buf][(wm * 64 + mt * 16 + lrow) * PROJ_SAS + lhalf * 16]);
            LDSM_X4(af[mt][0], af[mt][1], af[mt][2], af[mt][3], a);
        }
        uint32_t bq[2][4];
        #pragma unroll
        for (int bp = 0; bp < 2; bp++) {
            uint32_t a = smem_u32(&sB[buf][(wn * 32 + bp * 16 + lrow) * PROJ_SAS + lhalf * 16]);
            LDSM_X4(bq[bp][0], bq[bp][1], bq[bp][2], bq[bp][3], a);
        }
        #pragma unroll
        for (int mt = 0; mt < 4; mt++)
            #pragma unroll
            for (int nt = 0; nt < 4; nt++) {
                const int bp = nt >> 1, sel = nt & 1;
                MMA_S8(acc[mt][nt][0], acc[mt][nt][1], acc[mt][nt][2], acc[mt][nt][3],
                       af[mt][0], af[mt][1], af[mt][2], af[mt][3],
                       bq[bp][sel], bq[bp][2 + sel]);
            }
    }

    const float wsc = g_scale[3] * 0.0078125f;
    #pragma unroll
    for (int mt = 0; mt < 4; mt++) {
        const int mlo = blockIdx.y * 128 + wm * 64 + mt * 16 + (lane >> 2);
        const int mhi = mlo + 8;
        const float sclo = wsc * g_gctx[mlo];
        const float schi = wsc * g_gctx[mhi];
        #pragma unroll
        for (int nt = 0; nt < 4; nt++) {
            const int n = blockIdx.x * 128 + wn * 32 + nt * 8 + (lane & 3) * 2;
            const float b0 = o_bias[n], b1 = o_bias[n + 1];
            *reinterpret_cast<float2*>(&out[(size_t)mlo * EE + n]) =
                make_float2((float)acc[mt][nt][0] * sclo + b0,
                            (float)acc[mt][nt][1] * sclo + b1);
            *reinterpret_cast<float2*>(&out[(size_t)mhi * EE + n]) =
                make_float2((float)acc[mt][nt][2] * schi + b0,
                            (float)acc[mt][nt][3] * schi + b1);
        }
    }
}

// ---------------- 6) flash attention, fp16 mma, 128-key chunks -----------------
// grid (qt=16, bh=64), 256 threads = 8 warps, warp owns 16 q rows.
// K/V chunks of 128 keys, double-buffered cp.async; 16 chunk iterations
// (halved barrier count vs 64-key chunks). QK + PV both f32-accum.
#define QPADH 72                         // halfs per smem row (144 B)
#define KBUF_H (128 * QPADH)             // one 128-key tile
#define ATTN_SMEM_B ((128 * QPADH + 4 * KBUF_H) * 2)   // 92160 bytes

__global__ void __launch_bounds__(256, 2) k_attn() {
    extern __shared__ __align__(16) __half hsm[];
    __half* sQ  = hsm;                       // 128 x QPADH
    __half* sK0 = hsm + 128 * QPADH;         // 2 x 128 x QPADH
    __half* sV0 = sK0 + 2 * KBUF_H;          // 2 x 128 x QPADH

    const int tid = threadIdx.x;
    const int wid = tid >> 5;
    const int lane = tid & 31;
    const int bh = blockIdx.y, qt = blockIdx.x;
    const int lr = lane >> 2;
    const int lc = lane & 3;

    const __half* qp = g_projh + (size_t)bh * LL * DD + (size_t)qt * 128 * DD;
    const __half* kp = g_projh + (size_t)NTOK * EE + (size_t)bh * LL * DD;
    const __half* vp = g_projh + (size_t)2 * NTOK * EE + (size_t)bh * LL * DD;

    // prefetch K/V chunk 0 + stage Q (128 rows x 64 halfs = 1024 x 16B each)
    {
        const uint32_t sqb = smem_u32(sQ);
        const uint32_t skb = smem_u32(sK0);
        const uint32_t svb = smem_u32(sV0);
        #pragma unroll
        for (int rep = 0; rep < 4; rep++) {
            int i = tid + rep * 256;
            int r = i >> 3, c = i & 7;
            CP_ASYNC16(skb + r * 144 + c * 16, kp + r * 64 + c * 8);
            CP_ASYNC16(svb + r * 144 + c * 16, vp + r * 64 + c * 8);
            CP_ASYNC16(sqb + r * 144 + c * 16, qp + r * 64 + c * 8);
        }
        CP_COMMIT();
    }
    CP_WAIT0();
    __syncthreads();

    // Q A-fragments: 4 k-steps of 16 over d
    uint32_t qa[4][4];
    #pragma unroll
    for (int kk = 0; kk < 4; kk++) {
        uint32_t a = smem_u32(&sQ[(wid * 16 + (lane & 15)) * QPADH + kk * 16 + (lane >> 4) * 8]);
        LDSM_X4(qa[kk][0], qa[kk][1], qa[kk][2], qa[kk][3], a);
    }

    float o[8][4];
    #pragma unroll
    for (int j = 0; j < 8; j++)
        #pragma unroll
        for (int u = 0; u < 4; u++) o[j][u] = 0.f;
    float rowl0 = 0.f, rowl1 = 0.f;

    for (int kt = 0; kt < 16; kt++) {
        const int buf = kt & 1;
        if (kt > 0) {
            CP_WAIT0();
            __syncthreads();    // orders: chunk arrival AND prior reads of buf^1
        }
        if (kt + 1 < 16) {
            const uint32_t skb = smem_u32(sK0 + (buf ^ 1) * KBUF_H);
            const uint32_t svb = smem_u32(sV0 + (buf ^ 1) * KBUF_H);
            const __half* kg = kp + (size_t)(kt + 1) * 128 * DD;
            const __half* vg = vp + (size_t)(kt + 1) * 128 * DD;
            #pragma unroll
            for (int rep = 0; rep < 4; rep++) {
                int i = tid + rep * 256;
                int r = i >> 3, c = i & 7;
                CP_ASYNC16(skb + r * 144 + c * 16, kg + r * 64 + c * 8);
                CP_ASYNC16(svb + r * 144 + c * 16, vg + r * 64 + c * 8);
            }
            CP_COMMIT();
        }

        const __half* Kb = sK0 + buf * KBUF_H;
        const __half* Vb = sV0 + buf * KBUF_H;

        // ---- S = Q K^T over 16 n-tiles (128 keys), exp, pack PV A-frags ----
        uint32_t pa[8][4];
        #pragma unroll
        for (int j = 0; j < 16; j++) {
            uint32_t kb[8];
            uint32_t a0 = smem_u32(&Kb[(j * 8 + (lane & 7)) * QPADH + ((lane >> 3) & 3) * 8]);
            LDSM_X4(kb[0], kb[1], kb[2], kb[3], a0);
            LDSM_X4(kb[4], kb[5], kb[6], kb[7], a0 + 64);   // +32 halfs
            float s0 = 0.f, s1 = 0.f, s2 = 0.f, s3 = 0.f;
            #pragma unroll
            for (int kk = 0; kk < 4; kk++)
                MMA_F16(s0, s1, s2, s3,
                        qa[kk][0], qa[kk][1], qa[kk][2], qa[kk][3],
                        kb[2 * kk], kb[2 * kk + 1]);
            float p0, p1, p2, p3;
            EX2F(p0, s0); EX2F(p1, s1); EX2F(p2, s2); EX2F(p3, s3);
            rowl0 += p0 + p1;
            rowl1 += p2 + p3;
            const int t = j >> 1, hf = (j & 1) * 2;
            PACK_F16X2(pa[t][hf],     p0, p1);
            PACK_F16X2(pa[t][hf + 1], p2, p3);
        }

        // ---- O += P V over 8 k16-steps (128 keys) ----
        #pragma unroll
        for (int j = 0; j < 8; j++) {
            #pragma unroll
            for (int kk = 0; kk < 8; kk++) {
                uint32_t vb[2];
                // V rows kk*16 + {lane, ...}: trans ldmatrix x2 per k-step
                uint32_t a0 = smem_u32(&Vb[(kk * 16 + (lane & 15)) * QPADH + j * 8]);
                asm volatile("ldmatrix.sync.aligned.m8n8.x2.trans.shared.b16 {%0,%1}, [%2];"
                    : "=r"(vb[0]), "=r"(vb[1]) : "r"(a0));
                MMA_F16(o[j][0], o[j][1], o[j][2], o[j][3],
                        pa[kk][0], pa[kk][1], pa[kk][2], pa[kk][3],
                        vb[0], vb[1]);
            }
        }
    }

    // ---- epilogue: reduce l across the quad, normalize, store ----
    {
        rowl0 += __shfl_xor_sync(~0u, rowl0, 1);
        rowl0 += __shfl_xor_sync(~0u, rowl0, 2);
        rowl1 += __shfl_xor_sync(~0u, rowl1, 1);
        rowl1 += __shfl_xor_sync(~0u, rowl1, 2);
        const int b_ = bh >> 4, h = bh & 15;
        const int r0 = wid * 16 + lr;
        const float inv0 = 1.f / rowl0, inv1 = 1.f / rowl1;
        float* base0 = g_ctx + ((size_t)b_ * LL + (size_t)qt * 128 + r0) * EE + h * 64;
        float* base1 = base0 + 8 * EE;
        #pragma unroll
        for (int j = 0; j < 8; j++) {
            *reinterpret_cast<float2*>(base0 + j * 8 + 2 * lc) =
                make_float2(o[j][0] * inv0, o[j][1] * inv0);
            *reinterpret_cast<float2*>(base1 + j * 8 + 2 * lc) =
                make_float2(o[j][2] * inv1, o[j][3] * inv1);
        }
    }
}

// ---------------- host launcher ----------------------------------------------
extern "C" void kernel_launch(void* const* d_in, const int* in_sizes, int n_in,
                              void* d_out, int out_size) {
    const float* query = (const float*)d_in[0];
    const float* key   = (const float*)d_in[1];
    const float* value = (const float*)d_in[2];
    const float* ipw   = (const float*)d_in[3];
    const float* ipb   = (const float*)d_in[4];
    const float* opw   = (const float*)d_in[5];
    const float* opb   = (const float*)d_in[6];
    float* out = (float*)d_out;

    cudaFuncSetAttribute(k_attn, cudaFuncAttributeMaxDynamicSharedMemorySize, ATTN_SMEM_B);

    k_wsum<<<dim3(256, 4), 256>>>(ipw, opw);
    k_wquant<<<4096, 256>>>(ipw, opw);

    k_actq_in<<<dim3(NTOK / 8, 3), 256>>>(query, key, value);

    k_proj8<<<dim3(8, 64, 3), 256>>>(ipb);

    k_attn<<<dim3(16, 64), 256, ATTN_SMEM_B>>>();

    k_actq_ctx<<<NTOK / 8, 256>>>();
    k_oproj8<<<dim3(8, 64), 256>>>(opb, out);
}

// round 16
// speedup vs baseline: 1.6783x; 1.6783x over previous
#include <cuda_runtime.h>
#include <cuda_fp16.h>
#include <cstdint>

#define BB 4
#define LL 2048
#define EE 1024
#define HH 16
#define DD 64
#define NTOK 8192            // BB*LL
#define WELEM 1048576        // EE*EE

// ---------------- scratch (device globals; no allocation allowed) -------------
__device__ __align__(16) float  g_partial[1024];
__device__ __align__(16) float  g_scale[4];
__device__ __align__(16) __half g_qwh[4 * WELEM];          // ternary weights as fp16
__device__ __align__(16) __half g_qxh[3 * NTOK * EE];      // quantized activations as fp16
__device__ __align__(16) float  g_gamma[3 * NTOK];
__device__ __align__(16) __half g_projh[3 * NTOK * EE];    // q/k/v proj fp16 [B][H][L][D]
__device__ __align__(16) float  g_ctx[NTOK * EE];          // attention output [B][L][E]
__device__ __align__(16) __half g_qctxh[NTOK * EE];        // quantized ctx as fp16
__device__ __align__(16) float  g_gctx[NTOK];

// ---------------- PTX helpers (standard sm_80+ instructions only) -------------
__device__ __forceinline__ uint32_t smem_u32(const void* p) {
    uint32_t a;
    asm("{ .reg .u64 t; cvta.to.shared.u64 t, %1; cvt.u32.u64 %0, t; }" : "=r"(a) : "l"(p));
    return a;
}
#define MMA_F16(c0, c1, c2, c3, a0, a1, a2, a3, b0, b1) \
    asm volatile("mma.sync.aligned.m16n8k16.row.col.f32.f16.f16.f32 " \
        "{%0,%1,%2,%3}, {%4,%5,%6,%7}, {%8,%9}, {%0,%1,%2,%3};" \
        : "+f"(c0), "+f"(c1), "+f"(c2), "+f"(c3) \
        : "r"(a0), "r"(a1), "r"(a2), "r"(a3), "r"(b0), "r"(b1))
#define LDSM_X4(r0, r1, r2, r3, a) \
    asm volatile("ldmatrix.sync.aligned.m8n8.x4.shared.b16 {%0,%1,%2,%3}, [%4];" \
        : "=r"(r0), "=r"(r1), "=r"(r2), "=r"(r3) : "r"(a))
#define LDSM_X4_T(r0, r1, r2, r3, a) \
    asm volatile("ldmatrix.sync.aligned.m8n8.x4.trans.shared.b16 {%0,%1,%2,%3}, [%4];" \
        : "=r"(r0), "=r"(r1), "=r"(r2), "=r"(r3) : "r"(a))
// d = f16x2 {lo, hi}
#define PACK_F16X2(d, lo, hi) \
    asm("cvt.rn.f16x2.f32 %0, %1, %2;" : "=r"(d) : "f"(hi), "f"(lo))
#define EX2F(d, x) asm("ex2.approx.f32 %0, %1;" : "=f"(d) : "f"(x))
#define CP_ASYNC16(saddr, gaddr) \
    asm volatile("cp.async.cg.shared.global [%0], [%1], 16;" :: "r"(saddr), "l"(gaddr))
#define CP_COMMIT()  asm volatile("cp.async.commit_group;" ::: "memory")
#define CP_WAIT0()   asm volatile("cp.async.wait_group 0;" ::: "memory")

// ---------------- 1) weight abs-sum partials (256 blocks per tensor) ----------
__global__ void k_wsum(const float* __restrict__ inw, const float* __restrict__ outw) {
    int w = blockIdx.y;
    const float4* p = reinterpret_cast<const float4*>((w < 3) ? inw + (size_t)w * WELEM : outw);
    const int chunk4 = WELEM / 4 / 256;
    int base = blockIdx.x * chunk4;
    float s = 0.f;
    for (int i = threadIdx.x; i < chunk4; i += 256) {
        float4 v = p[base + i];
        s += fabsf(v.x) + fabsf(v.y) + fabsf(v.z) + fabsf(v.w);
    }
    #pragma unroll
    for (int st = 16; st; st >>= 1) s += __shfl_xor_sync(~0u, s, st);
    __shared__ float sm[8];
    if ((threadIdx.x & 31) == 0) sm[threadIdx.x >> 5] = s;
    __syncthreads();
    if (threadIdx.x == 0) {
        float tot = 0.f;
        #pragma unroll
        for (int i = 0; i < 8; i++) tot += sm[i];
        g_partial[w * 256 + blockIdx.x] = tot;
    }
}

// ---------------- 3) ternarize weights -> fp16; scale reduced in-block --------
__global__ void k_wquant(const float* __restrict__ inw, const float* __restrict__ outw) {
    const int w = (int)(blockIdx.x >> 10);
    float s = g_partial[w * 256 + threadIdx.x];
    #pragma unroll
    for (int st = 16; st; st >>= 1) s += __shfl_xor_sync(~0u, s, st);
    __shared__ float sm[8];
    if ((threadIdx.x & 31) == 0) sm[threadIdx.x >> 5] = s;
    __syncthreads();
    float tot = sm[0];
    #pragma unroll
    for (int i = 1; i < 8; i++) tot += sm[i];
    const float scale = fmaxf(tot * (1.f / (float)WELEM), 1e-5f);
    if ((blockIdx.x & 1023) == 0 && threadIdx.x == 0) g_scale[w] = scale;

    int idx4 = blockIdx.x * 256 + threadIdx.x;
    int idx = idx4 * 4;
    float4 v = (idx < 3 * WELEM)
        ? reinterpret_cast<const float4*>(inw)[idx4]
        : reinterpret_cast<const float4*>(outw)[idx4 - 3 * WELEM / 4];
    float inv = 1.f / scale;
    float q0 = fmaxf(-1.f, fminf(1.f, rintf(v.x * inv)));
    float q1 = fmaxf(-1.f, fminf(1.f, rintf(v.y * inv)));
    float q2 = fmaxf(-1.f, fminf(1.f, rintf(v.z * inv)));
    float q3 = fmaxf(-1.f, fminf(1.f, rintf(v.w * inv)));
    uint2 pk;
    PACK_F16X2(pk.x, q0, q1);
    PACK_F16X2(pk.y, q2, q3);
    reinterpret_cast<uint2*>(g_qwh)[idx4] = pk;
}

// ---------------- 4) activation quantization -> fp16 (warp-per-token) ---------
__device__ __forceinline__ void actq_warp(const float* xp, __half* qx, float* gam,
                                          int t, int lane) {
    const float4* x4 = reinterpret_cast<const float4*>(xp);
    float4 v4[8];
    float m = 0.f;
    #pragma unroll
    for (int i = 0; i < 8; i++) {
        v4[i] = x4[lane + i * 32];
        m = fmaxf(m, fmaxf(fmaxf(fabsf(v4[i].x), fabsf(v4[i].y)),
                           fmaxf(fabsf(v4[i].z), fabsf(v4[i].w))));
    }
    #pragma unroll
    for (int w = 16; w; w >>= 1) m = fmaxf(m, __shfl_xor_sync(~0u, m, w));
    float gamma = fmaxf(m, 1e-5f);
    float inv = 128.f / gamma;
    uint2* q4 = reinterpret_cast<uint2*>(qx);
    #pragma unroll
    for (int i = 0; i < 8; i++) {
        float q0 = fmaxf(-128.f, fminf(127.f, rintf(v4[i].x * inv)));
        float q1 = fmaxf(-128.f, fminf(127.f, rintf(v4[i].y * inv)));
        float q2 = fmaxf(-128.f, fminf(127.f, rintf(v4[i].z * inv)));
        float q3 = fmaxf(-128.f, fminf(127.f, rintf(v4[i].w * inv)));
        uint2 pk;
        PACK_F16X2(pk.x, q0, q1);
        PACK_F16X2(pk.y, q2, q3);
        q4[lane + i * 32] = pk;
    }
    if (lane == 0) gam[t] = gamma;
}

__global__ void k_actq_in(const float* __restrict__ q, const float* __restrict__ k,
                          const float* __restrict__ v) {
    int slot = blockIdx.y;
    const float* x = (slot == 0) ? q : (slot == 1) ? k : v;
    int wid = threadIdx.x >> 5, lane = threadIdx.x & 31;
    int t = blockIdx.x * 8 + wid;
    actq_warp(x + (size_t)t * EE,
              g_qxh + (size_t)slot * NTOK * EE + (size_t)t * EE,
              g_gamma + slot * NTOK, t, lane);
}

__global__ void k_actq_ctx() {
    int wid = threadIdx.x >> 5, lane = threadIdx.x & 31;
    int t = blockIdx.x * 8 + wid;
    actq_warp(g_ctx + (size_t)t * EE, g_qctxh + (size_t)t * EE, g_gctx, t, lane);
}

// ---------------- 5/7) projection GEMMs via fp16 HMMA (bit-exact int math) ----
// Tile 128m x 128n, K chunks of 64, fp16 operands (integer-valued), f32 accum.
// smem pitch 72 halfs (144 B) -> conflict-free ldmatrix (same as attention).
#define PR 72
#define PTILE_H (128 * PR)                       // halfs per tile buffer
#define PROJ_SMEM_B (4 * PTILE_H * 2)            // 73728 bytes

// core: computes acc (fp32, exact ints) for A[my*128.. ][1024] * B[nx*128..][1024]^T
__device__ __forceinline__ void gemm16_core(
    const __half* Ag, const __half* Bg, __half* sbase, float acc[4][4][4],
    int wm, int wn, int lane, int tid)
{
    __half* sA0 = sbase;                  // 2 x PTILE_H
    __half* sB0 = sbase + 2 * PTILE_H;    // 2 x PTILE_H

    // prefetch chunk 0 (both tiles): 128 rows x 64 halfs = 1024 x 16B each
    {
        const uint32_t sa = smem_u32(sA0);
        const uint32_t sb = smem_u32(sB0);
        #pragma unroll
        for (int rep = 0; rep < 4; rep++) {
            int i = tid + rep * 256;
            int r = i >> 3, c = i & 7;
            CP_ASYNC16(sa + r * 144 + c * 16, Ag + (size_t)r * EE + c * 8);
            CP_ASYNC16(sb + r * 144 + c * 16, Bg + (size_t)r * EE + c * 8);
        }
        CP_COMMIT();
    }

    for (int kt = 0; kt < 16; kt++) {
        const int buf = kt & 1;
        CP_WAIT0();
        __syncthreads();
        if (kt + 1 < 16) {
            const uint32_t sa = smem_u32(sA0 + (buf ^ 1) * PTILE_H);
            const uint32_t sb = smem_u32(sB0 + (buf ^ 1) * PTILE_H);
            const __half* Agn = Ag + (kt + 1) * 64;
            const __half* Bgn = Bg + (kt + 1) * 64;
            #pragma unroll
            for (int rep = 0; rep < 4; rep++) {
                int i = tid + rep * 256;
                int r = i >> 3, c = i & 7;
                CP_ASYNC16(sa + r * 144 + c * 16, Agn + (size_t)r * EE + c * 8);
                CP_ASYNC16(sb + r * 144 + c * 16, Bgn + (size_t)r * EE + c * 8);
            }
            CP_COMMIT();
        }
        const __half* As = sA0 + buf * PTILE_H;
        const __half* Bs = sB0 + buf * PTILE_H;

        // B fragments for all 4 n8-tiles over the whole 64-k chunk
        uint32_t bq[4][8];
        #pragma unroll
        for (int j = 0; j < 4; j++) {
            uint32_t a0 = smem_u32(&Bs[(wn * 32 + j * 8 + (lane & 7)) * PR + ((lane >> 3) & 3) * 8]);
            LDSM_X4(bq[j][0], bq[j][1], bq[j][2], bq[j][3], a0);
            LDSM_X4(bq[j][4], bq[j][5], bq[j][6], bq[j][7], a0 + 64);   // +32 halfs
        }
        #pragma unroll
        for (int kk = 0; kk < 4; kk++) {
            uint32_t af[4][4];
            #pragma unroll
            for (int mt = 0; mt < 4; mt++) {
                uint32_t a = smem_u32(&As[(wm * 64 + mt * 16 + (lane & 15)) * PR
                                          + kk * 16 + (lane >> 4) * 8]);
                LDSM_X4(af[mt][0], af[mt][1], af[mt][2], af[mt][3], a);
            }
            #pragma unroll
            for (int mt = 0; mt < 4; mt++)
                #pragma unroll
                for (int j = 0; j < 4; j++)
                    MMA_F16(acc[mt][j][0], acc[mt][j][1], acc[mt][j][2], acc[mt][j][3],
                            af[mt][0], af[mt][1], af[mt][2], af[mt][3],
                            bq[j][2 * kk], bq[j][2 * kk + 1]);
        }
        __syncthreads();
    }
}

__global__ void __launch_bounds__(256) k_proj16(const float* __restrict__ in_bias) {
    extern __shared__ __align__(16) __half psm[];
    const int z = blockIdx.z;
    const __half* Ag = g_qxh + (size_t)z * NTOK * EE + (size_t)blockIdx.y * 128 * EE;
    const __half* Bg = g_qwh + (size_t)z * WELEM + (size_t)blockIdx.x * 128 * EE;
    const int tid = threadIdx.x, wid = tid >> 5, lane = tid & 31;
    const int wm = wid & 1, wn = wid >> 1;

    float acc[4][4][4];
    #pragma unroll
    for (int a = 0; a < 4; a++)
        #pragma unroll
        for (int b = 0; b < 4; b++)
            #pragma unroll
            for (int c = 0; c < 4; c++) acc[a][b][c] = 0.f;

    gemm16_core(Ag, Bg, psm, acc, wm, wn, lane, tid);

    const float qmul = (z == 0) ? 0.125f * 1.4426950408889634f : 1.f;
    const float wsc = g_scale[z] * 0.0078125f * qmul;   // /128
    __half* outp = g_projh + (size_t)z * NTOK * EE;
    #pragma unroll
    for (int mt = 0; mt < 4; mt++) {
        const int mlo = blockIdx.y * 128 + wm * 64 + mt * 16 + (lane >> 2);
        const int mhi = mlo + 8;
        const float sclo = wsc * g_gamma[z * NTOK + mlo];
        const float schi = wsc * g_gamma[z * NTOK + mhi];
        const int blo = mlo >> 11, llo = mlo & 2047;
        const int bhi = mhi >> 11, lhi = mhi & 2047;
        #pragma unroll
        for (int nt = 0; nt < 4; nt++) {
            const int n = blockIdx.x * 128 + wn * 32 + nt * 8 + (lane & 3) * 2;
            const int h = n >> 6, d = n & 63;
            const float fb0 = in_bias[z * EE + n] * qmul;
            const float fb1 = in_bias[z * EE + n + 1] * qmul;
            float v0 = acc[mt][nt][0] * sclo + fb0;
            float v1 = acc[mt][nt][1] * sclo + fb1;
            float v2 = acc[mt][nt][2] * schi + fb0;
            float v3 = acc[mt][nt][3] * schi + fb1;
            uint32_t plo, phi;
            PACK_F16X2(plo, v0, v1);
            PACK_F16X2(phi, v2, v3);
            *reinterpret_cast<uint32_t*>(
                &outp[((size_t)(blo * HH + h) * LL + llo) * DD + d]) = plo;
            *reinterpret_cast<uint32_t*>(
                &outp[((size_t)(bhi * HH + h) * LL + lhi) * DD + d]) = phi;
        }
    }
}

__global__ void __launch_bounds__(256) k_oproj16(const float* __restrict__ o_bias,
                                                 float* __restrict__ out) {
    extern __shared__ __align__(16) __half psm[];
    const __half* Ag = g_qctxh + (size_t)blockIdx.y * 128 * EE;
    const __half* Bg = g_qwh + (size_t)3 * WELEM + (size_t)blockIdx.x * 128 * EE;
    const int tid = threadIdx.x, wid = tid >> 5, lane = tid & 31;
    const int wm = wid & 1, wn = wid >> 1;

    float acc[4][4][4];
    #pragma unroll
    for (int a = 0; a < 4; a++)
        #pragma unroll
        for (int b = 0; b < 4; b++)
            #pragma unroll
            for (int c = 0; c < 4; c++) acc[a][b][c] = 0.f;

    gemm16_core(Ag, Bg, psm, acc, wm, wn, lane, tid);

    const float wsc = g_scale[3] * 0.0078125f;
    #pragma unroll
    for (int mt = 0; mt < 4; mt++) {
        const int mlo = blockIdx.y * 128 + wm * 64 + mt * 16 + (lane >> 2);
        const int mhi = mlo + 8;
        const float sclo = wsc * g_gctx[mlo];
        const float schi = wsc * g_gctx[mhi];
        #pragma unroll
        for (int nt = 0; nt < 4; nt++) {
            const int n = blockIdx.x * 128 + wn * 32 + nt * 8 + (lane & 3) * 2;
            const float b0 = o_bias[n], b1 = o_bias[n + 1];
            *reinterpret_cast<float2*>(&out[(size_t)mlo * EE + n]) =
                make_float2(acc[mt][nt][0] * sclo + b0, acc[mt][nt][1] * sclo + b1);
            *reinterpret_cast<float2*>(&out[(size_t)mhi * EE + n]) =
                make_float2(acc[mt][nt][2] * schi + b0, acc[mt][nt][3] * schi + b1);
        }
    }
}

// ---------------- 6) flash attention, fp16 mma m16n8k16 (R13 version) ----------
// grid (qt=16, bh=64), 256 threads = 8 warps, warp owns 16 q rows.
// K/V chunks of 64 keys, double-buffered cp.async (one barrier per chunk).
#define QPADH 72                         // halfs per smem row (144 B)
#define KBUF_H (64 * QPADH)
#define ATTN_SMEM_B ((128 * QPADH + 4 * KBUF_H) * 2)   // 55296 bytes

__global__ void __launch_bounds__(256, 2) k_attn() {
    extern __shared__ __align__(16) __half hsm[];
    __half* sQ  = hsm;                       // 128 x QPADH
    __half* sK0 = hsm + 128 * QPADH;         // 2 x 64 x QPADH
    __half* sV0 = sK0 + 2 * KBUF_H;          // 2 x 64 x QPADH

    const int tid = threadIdx.x;
    const int wid = tid >> 5;
    const int lane = tid & 31;
    const int bh = blockIdx.y, qt = blockIdx.x;
    const int lr = lane >> 2;
    const int lc = lane & 3;

    const __half* qp = g_projh + (size_t)bh * LL * DD + (size_t)qt * 128 * DD;
    const __half* kp = g_projh + (size_t)NTOK * EE + (size_t)bh * LL * DD;
    const __half* vp = g_projh + (size_t)2 * NTOK * EE + (size_t)bh * LL * DD;

    // prefetch K/V chunk 0 + stage Q
    {
        const uint32_t sqb = smem_u32(sQ);
        const uint32_t skb = smem_u32(sK0);
        const uint32_t svb = smem_u32(sV0);
        #pragma unroll
        for (int rep = 0; rep < 2; rep++) {
            int i = tid + rep * 256;
            int r = i >> 3, c = i & 7;
            CP_ASYNC16(skb + r * 144 + c * 16, kp + r * 64 + c * 8);
            CP_ASYNC16(svb + r * 144 + c * 16, vp + r * 64 + c * 8);
        }
        #pragma unroll
        for (int rep = 0; rep < 4; rep++) {
            int i = tid + rep * 256;
            int r = i >> 3, c = i & 7;
            CP_ASYNC16(sqb + r * 144 + c * 16, qp + r * 64 + c * 8);
        }
        CP_COMMIT();
    }
    CP_WAIT0();
    __syncthreads();

    // Q A-fragments: 4 k-steps of 16 over d
    uint32_t qa[4][4];
    #pragma unroll
    for (int kk = 0; kk < 4; kk++) {
        uint32_t a = smem_u32(&sQ[(wid * 16 + (lane & 15)) * QPADH + kk * 16 + (lane >> 4) * 8]);
        LDSM_X4(qa[kk][0], qa[kk][1], qa[kk][2], qa[kk][3], a);
    }

    float o[8][4];
    #pragma unroll
    for (int j = 0; j < 8; j++)
        #pragma unroll
        for (int u = 0; u < 4; u++) o[j][u] = 0.f;
    float rowl0 = 0.f, rowl1 = 0.f;

    for (int kt = 0; kt < 32; kt++) {
        const int buf = kt & 1;
        if (kt > 0) {
            CP_WAIT0();
            __syncthreads();    // orders: chunk arrival AND prior reads of buf^1
        }
        if (kt + 1 < 32) {
            const uint32_t skb = smem_u32(sK0 + (buf ^ 1) * KBUF_H);
            const uint32_t svb = smem_u32(sV0 + (buf ^ 1) * KBUF_H);
            const __half* kg = kp + (size_t)(kt + 1) * 64 * DD;
            const __half* vg = vp + (size_t)(kt + 1) * 64 * DD;
            #pragma unroll
            for (int rep = 0; rep < 2; rep++) {
                int i = tid + rep * 256;
                int r = i >> 3, c = i & 7;
                CP_ASYNC16(skb + r * 144 + c * 16, kg + r * 64 + c * 8);
                CP_ASYNC16(svb + r * 144 + c * 16, vg + r * 64 + c * 8);
            }
            CP_COMMIT();
        }

        const __half* Kb = sK0 + buf * KBUF_H;
        const __half* Vb = sV0 + buf * KBUF_H;

        // ---- S = Q K^T, exp, pack into PV A-fragments (registers only) ----
        uint32_t pa[4][4];
        #pragma unroll
        for (int j = 0; j < 8; j++) {
            uint32_t kb[8];
            uint32_t a0 = smem_u32(&Kb[(j * 8 + (lane & 7)) * QPADH + ((lane >> 3) & 3) * 8]);
            LDSM_X4(kb[0], kb[1], kb[2], kb[3], a0);
            LDSM_X4(kb[4], kb[5], kb[6], kb[7], a0 + 64);   // +32 halfs
            float s0 = 0.f, s1 = 0.f, s2 = 0.f, s3 = 0.f;
            #pragma unroll
            for (int kk = 0; kk < 4; kk++)
                MMA_F16(s0, s1, s2, s3,
                        qa[kk][0], qa[kk][1], qa[kk][2], qa[kk][3],
                        kb[2 * kk], kb[2 * kk + 1]);
            float p0, p1, p2, p3;
            EX2F(p0, s0); EX2F(p1, s1); EX2F(p2, s2); EX2F(p3, s3);
            rowl0 += p0 + p1;
            rowl1 += p2 + p3;
            const int t = j >> 1, hf = (j & 1) * 2;
            PACK_F16X2(pa[t][hf],     p0, p1);
            PACK_F16X2(pa[t][hf + 1], p2, p3);
        }

        // ---- O += P V ----
        #pragma unroll
        for (int j = 0; j < 8; j++) {
            uint32_t vb[8];
            uint32_t a0 = smem_u32(&Vb[lane * QPADH + j * 8]);
            uint32_t a1 = smem_u32(&Vb[(32 + lane) * QPADH + j * 8]);
            LDSM_X4_T(vb[0], vb[1], vb[2], vb[3], a0);
            LDSM_X4_T(vb[4], vb[5], vb[6], vb[7], a1);
            #pragma unroll
            for (int kk = 0; kk < 4; kk++)
                MMA_F16(o[j][0], o[j][1], o[j][2], o[j][3],
                        pa[kk][0], pa[kk][1], pa[kk][2], pa[kk][3],
                        vb[2 * kk], vb[2 * kk + 1]);
        }
    }

    // ---- epilogue: reduce l across the quad, normalize, store ----
    {
        rowl0 += __shfl_xor_sync(~0u, rowl0, 1);
        rowl0 += __shfl_xor_sync(~0u, rowl0, 2);
        rowl1 += __shfl_xor_sync(~0u, rowl1, 1);
        rowl1 += __shfl_xor_sync(~0u, rowl1, 2);
        const int b_ = bh >> 4, h = bh & 15;
        const int r0 = wid * 16 + lr;
        const float inv0 = 1.f / rowl0, inv1 = 1.f / rowl1;
        float* base0 = g_ctx + ((size_t)b_ * LL + (size_t)qt * 128 + r0) * EE + h * 64;
        float* base1 = base0 + 8 * EE;
        #pragma unroll
        for (int j = 0; j < 8; j++) {
            *reinterpret_cast<float2*>(base0 + j * 8 + 2 * lc) =
                make_float2(o[j][0] * inv0, o[j][1] * inv0);
            *reinterpret_cast<float2*>(base1 + j * 8 + 2 * lc) =
                make_float2(o[j][2] * inv1, o[j][3] * inv1);
        }
    }
}

// ---------------- host launcher ----------------------------------------------
extern "C" void kernel_launch(void* const* d_in, const int* in_sizes, int n_in,
                              void* d_out, int out_size) {
    const float* query = (const float*)d_in[0];
    const float* key   = (const float*)d_in[1];
    const float* value = (const float*)d_in[2];
    const float* ipw   = (const float*)d_in[3];
    const float* ipb   = (const float*)d_in[4];
    const float* opw   = (const float*)d_in[5];
    const float* opb   = (const float*)d_in[6];
    float* out = (float*)d_out;

    cudaFuncSetAttribute(k_attn, cudaFuncAttributeMaxDynamicSharedMemorySize, ATTN_SMEM_B);
    cudaFuncSetAttribute(k_proj16, cudaFuncAttributeMaxDynamicSharedMemorySize, PROJ_SMEM_B);
    cudaFuncSetAttribute(k_oproj16, cudaFuncAttributeMaxDynamicSharedMemorySize, PROJ_SMEM_B);

    k_wsum<<<dim3(256, 4), 256>>>(ipw, opw);
    k_wquant<<<4096, 256>>>(ipw, opw);

    k_actq_in<<<dim3(NTOK / 8, 3), 256>>>(query, key, value);

    k_proj16<<<dim3(8, 64, 3), 256, PROJ_SMEM_B>>>(ipb);

    k_attn<<<dim3(16, 64), 256, ATTN_SMEM_B>>>();

    k_actq_ctx<<<NTOK / 8, 256>>>();
    k_oproj16<<<dim3(8, 64), 256, PROJ_SMEM_B>>>(opb, out);
}